// round 3
// baseline (speedup 1.0000x reference)
#include <cuda_runtime.h>
#include <math.h>

#define T_SEQ 512
#define BATCH 64
#define HDIM  512
#define EDIM  300
#define G3    1536   // 3*H
#define NCOLS 4608   // 3 * G3
#define NB    144    // persistent grid: 72 n-tiles x 2 k-halves (<=148 SMs, 1 CTA/SM)

// ---------------- device scratch (no allocations) ----------------
__device__ float g_xp0[T_SEQ * BATCH * G3];    // [t*64+b][g] layer-0 input projections
__device__ float g_gh [2 * BATCH * NCOLS];     // split-K partial GEMM outputs
__device__ float g_h1h[T_SEQ * BATCH * HDIM];  // layer-0 hidden history
__device__ float g_h2h[T_SEQ * BATCH * HDIM];  // layer-1 hidden history
__device__ unsigned g_cnt;                     // grid barrier arrival counter
__device__ volatile unsigned g_gen;            // grid barrier generation

__device__ __forceinline__ float sigmoidf_(float x) { return 1.0f / (1.0f + expf(-x)); }

// packed f32x2 FMA (sm_103a FFMA2 — PTX-only)
__device__ __forceinline__ unsigned long long fma2_(unsigned long long a,
                                                    unsigned long long b,
                                                    unsigned long long c) {
    unsigned long long d;
    asm("fma.rn.f32x2 %0, %1, %2, %3;" : "=l"(d) : "l"(a), "l"(b), "l"(c));
    return d;
}
__device__ __forceinline__ float2 unpack2_(unsigned long long v) {
    float2 r;
    asm("mov.b64 {%0, %1}, %2;" : "=f"(r.x), "=f"(r.y) : "l"(v));
    return r;
}

// fenced spin grid barrier (all NB CTAs co-resident: 1 CTA/SM by smem)
__device__ __forceinline__ void grid_sync() {
    __syncthreads();
    if (threadIdx.x == 0) {
        unsigned old = g_gen;
        __threadfence();
        if (atomicAdd(&g_cnt, 1u) == NB - 1) {
            g_cnt = 0;
            __threadfence();
            g_gen = old + 1;
        } else {
            while (g_gen == old) { }
        }
        __threadfence();
    }
    __syncthreads();
}

// =====================================================================
// xp0[m][g] = emb[texts[m]] . Wih0[g] + bih0[g].  M=32768, N=1536, K=300.
// CTA 64m x 64n, micro 4x4 as 2 b-pairs x 4 cols in FFMA2. 15 K-chunks of 20.
// sA k-major [k][64] stride 68; sW2 duplicated [k][2*col] stride 132.
// =====================================================================
__global__ __launch_bounds__(256) void xp0_kernel(const int* __restrict__ texts,
                                                  const float* __restrict__ emb,
                                                  const float* __restrict__ Wih0,
                                                  const float* __restrict__ bih0) {
    __shared__ __align__(16) float sA [20 * 68];
    __shared__ __align__(16) float sW2[20 * 132];

    const int n0 = blockIdx.x * 64;
    const int m0 = blockIdx.y * 64;
    const int tid = threadIdx.x;
    const int mp = tid & 15;    // m = 4*mp + 2*bp + {0,1}
    const int np = tid >> 4;    // n = 4*np + j

    unsigned long long acc[2][4];
#pragma unroll
    for (int a = 0; a < 2; a++)
#pragma unroll
        for (int j = 0; j < 4; j++) acc[a][j] = 0ull;

    for (int c = 0; c < 15; ++c) {
        const int kb = c * 20;
        __syncthreads();
        for (int idx = tid; idx < 320; idx += 256) {   // 64 rows * 5 float4
            const int row = idx & 63;
            const int q   = idx >> 6;                  // 0..4
            const int tok = texts[m0 + row];
            float4 v = *reinterpret_cast<const float4*>(emb + tok * EDIM + kb + 4 * q);
            sA[(4 * q + 0) * 68 + row] = v.x;
            sA[(4 * q + 1) * 68 + row] = v.y;
            sA[(4 * q + 2) * 68 + row] = v.z;
            sA[(4 * q + 3) * 68 + row] = v.w;
            float4 w = *reinterpret_cast<const float4*>(Wih0 + (n0 + row) * EDIM + kb + 4 * q);
            *reinterpret_cast<float2*>(&sW2[(4 * q + 0) * 132 + 2 * row]) = make_float2(w.x, w.x);
            *reinterpret_cast<float2*>(&sW2[(4 * q + 1) * 132 + 2 * row]) = make_float2(w.y, w.y);
            *reinterpret_cast<float2*>(&sW2[(4 * q + 2) * 132 + 2 * row]) = make_float2(w.z, w.z);
            *reinterpret_cast<float2*>(&sW2[(4 * q + 3) * 132 + 2 * row]) = make_float2(w.w, w.w);
        }
        __syncthreads();
#pragma unroll 5
        for (int kk = 0; kk < 20; ++kk) {
            ulonglong2 A  = *reinterpret_cast<const ulonglong2*>(&sA [kk * 68  + 4 * mp]);
            ulonglong2 Wa = *reinterpret_cast<const ulonglong2*>(&sW2[kk * 132 + 8 * np]);
            ulonglong2 Wb = *reinterpret_cast<const ulonglong2*>(&sW2[kk * 132 + 8 * np + 4]);
            acc[0][0] = fma2_(A.x, Wa.x, acc[0][0]);
            acc[0][1] = fma2_(A.x, Wa.y, acc[0][1]);
            acc[0][2] = fma2_(A.x, Wb.x, acc[0][2]);
            acc[0][3] = fma2_(A.x, Wb.y, acc[0][3]);
            acc[1][0] = fma2_(A.y, Wa.x, acc[1][0]);
            acc[1][1] = fma2_(A.y, Wa.y, acc[1][1]);
            acc[1][2] = fma2_(A.y, Wb.x, acc[1][2]);
            acc[1][3] = fma2_(A.y, Wb.y, acc[1][3]);
        }
    }

    float bi[4];
#pragma unroll
    for (int j = 0; j < 4; j++) bi[j] = bih0[n0 + 4 * np + j];
#pragma unroll
    for (int bp = 0; bp < 2; ++bp) {
        float2 u0 = unpack2_(acc[bp][0]);
        float2 u1 = unpack2_(acc[bp][1]);
        float2 u2 = unpack2_(acc[bp][2]);
        float2 u3 = unpack2_(acc[bp][3]);
        const int m = m0 + 4 * mp + 2 * bp;
        *reinterpret_cast<float4*>(&g_xp0[m * G3 + n0 + 4 * np]) =
            make_float4(u0.x + bi[0], u1.x + bi[1], u2.x + bi[2], u3.x + bi[3]);
        *reinterpret_cast<float4*>(&g_xp0[(m + 1) * G3 + n0 + 4 * np]) =
            make_float4(u0.y + bi[0], u1.y + bi[1], u2.y + bi[2], u3.y + bi[3]);
    }
}

// =====================================================================
// Gate nonlinearity, distributed across the persistent grid.
// =====================================================================
__device__ __forceinline__ void gate_phase(int iter, const float* bhh0,
                                           const float* bih1, const float* bhh1) {
    const int stride = NB * 256;
    for (int id = blockIdx.x * 256 + threadIdx.x; id < 2 * BATCH * HDIM; id += stride) {
        const int layer = id >> 15;
        const int b = (id >> 9) & 63;
        const int h = id & 511;
        const float* gha = g_gh + b * NCOLS;
        const float* ghb = g_gh + BATCH * NCOLS + b * NCOLS;

        if (layer == 0) {
            if (iter >= T_SEQ) continue;
            const float* xp = &g_xp0[(iter * BATCH + b) * G3];
            float hr = bhh0[h], hz = bhh0[HDIM + h], hn = bhh0[2 * HDIM + h];
            float hprev = 0.0f;
            if (iter > 0) {
                hr += gha[h]            + ghb[h];
                hz += gha[HDIM + h]     + ghb[HDIM + h];
                hn += gha[2 * HDIM + h] + ghb[2 * HDIM + h];
                hprev = g_h1h[((iter - 1) * BATCH + b) * HDIM + h];
            }
            float r = sigmoidf_(xp[h] + hr);
            float z = sigmoidf_(xp[HDIM + h] + hz);
            float n = tanhf(xp[2 * HDIM + h] + r * hn);
            g_h1h[(iter * BATCH + b) * HDIM + h] = (1.0f - z) * n + z * hprev;
        } else {
            if (iter < 1) continue;
            const int t = iter - 1;
            float xr = gha[G3 + h]            + ghb[G3 + h]            + bih1[h];
            float xz = gha[G3 + HDIM + h]     + ghb[G3 + HDIM + h]     + bih1[HDIM + h];
            float xn = gha[G3 + 2 * HDIM + h] + ghb[G3 + 2 * HDIM + h] + bih1[2 * HDIM + h];
            float hr = bhh1[h], hz = bhh1[HDIM + h], hn = bhh1[2 * HDIM + h];
            float hprev = 0.0f;
            if (t > 0) {
                hr += gha[2 * G3 + h]            + ghb[2 * G3 + h];
                hz += gha[2 * G3 + HDIM + h]     + ghb[2 * G3 + HDIM + h];
                hn += gha[2 * G3 + 2 * HDIM + h] + ghb[2 * G3 + 2 * HDIM + h];
                hprev = g_h2h[((t - 1) * BATCH + b) * HDIM + h];
            }
            float r = sigmoidf_(xr + hr);
            float z = sigmoidf_(xz + hz);
            float n = tanhf(xn + r * hn);
            g_h2h[(t * BATCH + b) * HDIM + h] = (1.0f - z) * n + z * hprev;
        }
    }
}

// =====================================================================
// Persistent recurrence kernel. 144 CTAs = 72 n-tiles(64) x 2 K-halves(256).
// Weight tile (64 cols x 256 k) lives DUPLICATED in smem for all 512 iters.
//   cols [0,1536):    h1[i-1] @ Whh0^T   (active 1<=i<=511)
//   cols [1536,3072): h1[i-1] @ Wih1^T   (active i>=1)
//   cols [3072,4608): h2[i-2] @ Whh1^T   (active i>=2)
// Dyn smem: sW2 [256][132] dup + sH [256][68] = 200 KB -> 1 CTA/SM.
// =====================================================================
#define SMEM_REC ((256 * 132 + 256 * 68) * 4)

__global__ __launch_bounds__(256) void recurrence_kernel(const float* __restrict__ Whh0,
                                                         const float* __restrict__ Wih1,
                                                         const float* __restrict__ Whh1,
                                                         const float* bhh0,
                                                         const float* bih1,
                                                         const float* bhh1) {
    extern __shared__ __align__(16) float dsm[];
    float* sW2 = dsm;              // [k<256][2*col], stride 132
    float* sH  = dsm + 256 * 132;  // [k<256][b],     stride 68

    const int tid = threadIdx.x;
    const int cta = blockIdx.x;
    const int nt = cta % 72;
    const int kt = cta / 72;
    const int n0 = nt * 64;
    const int k0 = kt * 256;
    const int mp = tid & 15;
    const int np = tid >> 4;

    const float* W;
    int wr0, cls;
    if (n0 < G3)          { W = Whh0; wr0 = n0;          cls = 0; }
    else if (n0 < 2 * G3) { W = Wih1; wr0 = n0 - G3;     cls = 1; }
    else                  { W = Whh1; wr0 = n0 - 2 * G3; cls = 2; }

    // ---- prologue: load this CTA's weight tile once, duplicated ----
    for (int idx = tid; idx < 4096; idx += 256) {       // 64 rows * 64 float4
        const int row = idx >> 6;                       // output col within tile
        const int q   = idx & 63;                       // float4 within 256-k
        float4 w = *reinterpret_cast<const float4*>(W + (wr0 + row) * HDIM + k0 + 4 * q);
        *reinterpret_cast<float2*>(&sW2[(4 * q + 0) * 132 + 2 * row]) = make_float2(w.x, w.x);
        *reinterpret_cast<float2*>(&sW2[(4 * q + 1) * 132 + 2 * row]) = make_float2(w.y, w.y);
        *reinterpret_cast<float2*>(&sW2[(4 * q + 2) * 132 + 2 * row]) = make_float2(w.z, w.z);
        *reinterpret_cast<float2*>(&sW2[(4 * q + 3) * 132 + 2 * row]) = make_float2(w.w, w.w);
    }
    __syncthreads();

    for (int iter = 0; iter <= T_SEQ; ++iter) {
        const bool active = (iter > 0) && !(cls == 0 && iter > 511) && !(cls == 2 && iter < 2);
        if (active) {
            const float* hsrc = (cls == 2) ? g_h2h + (iter - 2) * BATCH * HDIM
                                           : g_h1h + (iter - 1) * BATCH * HDIM;
            // fill h tile: 64 b-rows x 256 k, k-major / b-contiguous
            for (int idx = tid; idx < 4096; idx += 256) {
                const int row = idx & 63;
                const int q   = idx >> 6;               // 0..63
                float4 v = *reinterpret_cast<const float4*>(hsrc + row * HDIM + k0 + 4 * q);
                sH[(4 * q + 0) * 68 + row] = v.x;
                sH[(4 * q + 1) * 68 + row] = v.y;
                sH[(4 * q + 2) * 68 + row] = v.z;
                sH[(4 * q + 3) * 68 + row] = v.w;
            }
            __syncthreads();

            unsigned long long acc[2][4];
#pragma unroll
            for (int a = 0; a < 2; a++)
#pragma unroll
                for (int j = 0; j < 4; j++) acc[a][j] = 0ull;

#pragma unroll 8
            for (int k = 0; k < 256; ++k) {
                ulonglong2 A  = *reinterpret_cast<const ulonglong2*>(&sH [k * 68  + 4 * mp]);
                ulonglong2 Wa = *reinterpret_cast<const ulonglong2*>(&sW2[k * 132 + 8 * np]);
                ulonglong2 Wb = *reinterpret_cast<const ulonglong2*>(&sW2[k * 132 + 8 * np + 4]);
                acc[0][0] = fma2_(A.x, Wa.x, acc[0][0]);
                acc[0][1] = fma2_(A.x, Wa.y, acc[0][1]);
                acc[0][2] = fma2_(A.x, Wb.x, acc[0][2]);
                acc[0][3] = fma2_(A.x, Wb.y, acc[0][3]);
                acc[1][0] = fma2_(A.y, Wa.x, acc[1][0]);
                acc[1][1] = fma2_(A.y, Wa.y, acc[1][1]);
                acc[1][2] = fma2_(A.y, Wb.x, acc[1][2]);
                acc[1][3] = fma2_(A.y, Wb.y, acc[1][3]);
            }

            float* outp = g_gh + kt * BATCH * NCOLS;
#pragma unroll
            for (int bp = 0; bp < 2; ++bp) {
                float2 u0 = unpack2_(acc[bp][0]);
                float2 u1 = unpack2_(acc[bp][1]);
                float2 u2 = unpack2_(acc[bp][2]);
                float2 u3 = unpack2_(acc[bp][3]);
                const int b = 4 * mp + 2 * bp;
                *reinterpret_cast<float4*>(outp + b * NCOLS + n0 + 4 * np) =
                    make_float4(u0.x, u1.x, u2.x, u3.x);
                *reinterpret_cast<float4*>(outp + (b + 1) * NCOLS + n0 + 4 * np) =
                    make_float4(u0.y, u1.y, u2.y, u3.y);
            }
        }
        grid_sync();                       // partials visible
        gate_phase(iter, bhh0, bih1, bhh1);
        grid_sync();                       // h1/h2 visible for next iter
    }
}

// =====================================================================
// pooled[t][h] = mean_b h2[t][b][h];  out[t][l] = pooled . fc_W[l] + fc_b[l]
// =====================================================================
__global__ __launch_bounds__(512) void final_kernel(const float* __restrict__ fc_W,
                                                    const float* __restrict__ fc_b,
                                                    float* __restrict__ out) {
    __shared__ float pooled[HDIM];
    const int t = blockIdx.x;
    const int h = threadIdx.x;

    float s = 0.0f;
    const float* base = &g_h2h[t * BATCH * HDIM + h];
#pragma unroll 8
    for (int b = 0; b < BATCH; ++b) s += base[b * HDIM];
    pooled[h] = s * (1.0f / (float)BATCH);
    __syncthreads();

    const int w = h >> 5, lane = h & 31;
    if (w < 5) {
        float acc = 0.0f;
        for (int k = lane; k < HDIM; k += 32) acc += pooled[k] * fc_W[w * HDIM + k];
#pragma unroll
        for (int o = 16; o > 0; o >>= 1) acc += __shfl_xor_sync(0xFFFFFFFFu, acc, o);
        if (lane == 0) out[t * 5 + w] = acc + fc_b[w];
    }
}

// =====================================================================
extern "C" void kernel_launch(void* const* d_in, const int* in_sizes, int n_in,
                              void* d_out, int out_size) {
    const int*   texts = (const int*)  d_in[0];
    const float* emb   = (const float*)d_in[1];
    const float* Wih0  = (const float*)d_in[2];
    const float* Whh0  = (const float*)d_in[3];
    const float* bih0  = (const float*)d_in[4];
    const float* bhh0  = (const float*)d_in[5];
    const float* Wih1  = (const float*)d_in[6];
    const float* Whh1  = (const float*)d_in[7];
    const float* bih1  = (const float*)d_in[8];
    const float* bhh1  = (const float*)d_in[9];
    const float* fc_W  = (const float*)d_in[10];
    const float* fc_b  = (const float*)d_in[11];
    float* out = (float*)d_out;

    cudaFuncSetAttribute(recurrence_kernel,
                         cudaFuncAttributeMaxDynamicSharedMemorySize, SMEM_REC);

    xp0_kernel<<<dim3(24, 512), 256>>>(texts, emb, Wih0, bih0);
    recurrence_kernel<<<NB, 256, SMEM_REC>>>(Whh0, Wih1, Whh1, bhh0, bih1, bhh1);
    final_kernel<<<T_SEQ, 512>>>(fc_W, fc_b, out);
}

// round 5
// speedup vs baseline: 1.6731x; 1.6731x over previous
#include <cuda_runtime.h>
#include <cuda_bf16.h>
#include <math.h>
#include <stdint.h>

#define T_SEQ 512
#define BATCH 64
#define HDIM  512
#define EDIM  300
#define G3    1536   // 3*H
#define NCOLS 4608   // 3 * G3
#define NB    144    // persistent grid: 72 n-tiles x 2 k-halves, 1 CTA/SM

// ---------------- device scratch (no allocations) ----------------
__device__ float g_xp0[T_SEQ * BATCH * G3];    // layer-0 input projections
__device__ float g_gh [2 * BATCH * NCOLS];     // split-K partial GEMM outputs
__device__ float g_h1h[T_SEQ * BATCH * HDIM];  // layer-0 hidden history
__device__ float g_h2h[T_SEQ * BATCH * HDIM];  // layer-1 hidden history
__device__ unsigned g_cnt;
__device__ volatile unsigned g_gen;

__device__ __forceinline__ float sigmoidf_(float x) { return 1.0f / (1.0f + expf(-x)); }

// ---------------- fp32x2 helpers (xp0 kernel) ----------------
__device__ __forceinline__ unsigned long long fma2_(unsigned long long a,
                                                    unsigned long long b,
                                                    unsigned long long c) {
    unsigned long long d;
    asm("fma.rn.f32x2 %0, %1, %2, %3;" : "=l"(d) : "l"(a), "l"(b), "l"(c));
    return d;
}
__device__ __forceinline__ float2 unpack2_(unsigned long long v) {
    float2 r;
    asm("mov.b64 {%0, %1}, %2;" : "=f"(r.x), "=f"(r.y) : "l"(v));
    return r;
}

// ---------------- warp MMA helpers (sm_80+ PTX: valid on base sm_103) ----------------
__device__ __forceinline__ uint32_t smem_u32_(const void* p) {
    uint32_t a;
    asm("{ .reg .u64 t; cvta.to.shared.u64 t, %1; cvt.u32.u64 %0, t; }" : "=r"(a) : "l"(p));
    return a;
}
__device__ __forceinline__ void ldsm4_(uint32_t& a0, uint32_t& a1, uint32_t& a2,
                                       uint32_t& a3, uint32_t addr) {
    asm volatile("ldmatrix.sync.aligned.m8n8.x4.shared.b16 {%0,%1,%2,%3}, [%4];"
                 : "=r"(a0), "=r"(a1), "=r"(a2), "=r"(a3) : "r"(addr));
}
__device__ __forceinline__ void ldsm2_(uint32_t& b0, uint32_t& b1, uint32_t addr) {
    asm volatile("ldmatrix.sync.aligned.m8n8.x2.shared.b16 {%0,%1}, [%2];"
                 : "=r"(b0), "=r"(b1) : "r"(addr));
}
__device__ __forceinline__ void mma16816_(float* c, uint32_t a0, uint32_t a1,
                                          uint32_t a2, uint32_t a3,
                                          uint32_t b0, uint32_t b1) {
    asm volatile("mma.sync.aligned.m16n8k16.row.col.f32.bf16.bf16.f32 "
                 "{%0,%1,%2,%3}, {%4,%5,%6,%7}, {%8,%9}, {%0,%1,%2,%3};"
                 : "+f"(c[0]), "+f"(c[1]), "+f"(c[2]), "+f"(c[3])
                 : "r"(a0), "r"(a1), "r"(a2), "r"(a3), "r"(b0), "r"(b1));
}

// pack fp32x4 -> bf16 hi and lo uint2
__device__ __forceinline__ void split_hl_(float4 v, uint2& hi, uint2& lo) {
    __nv_bfloat16 h0 = __float2bfloat16(v.x), h1 = __float2bfloat16(v.y);
    __nv_bfloat16 h2 = __float2bfloat16(v.z), h3 = __float2bfloat16(v.w);
    __nv_bfloat16 l0 = __float2bfloat16(v.x - __bfloat162float(h0));
    __nv_bfloat16 l1 = __float2bfloat16(v.y - __bfloat162float(h1));
    __nv_bfloat16 l2 = __float2bfloat16(v.z - __bfloat162float(h2));
    __nv_bfloat16 l3 = __float2bfloat16(v.w - __bfloat162float(h3));
    hi = make_uint2(((uint32_t)__bfloat16_as_ushort(h1) << 16) | __bfloat16_as_ushort(h0),
                    ((uint32_t)__bfloat16_as_ushort(h3) << 16) | __bfloat16_as_ushort(h2));
    lo = make_uint2(((uint32_t)__bfloat16_as_ushort(l1) << 16) | __bfloat16_as_ushort(l0),
                    ((uint32_t)__bfloat16_as_ushort(l3) << 16) | __bfloat16_as_ushort(l2));
}

// ---------------- grid barrier ----------------
__device__ __forceinline__ void grid_sync() {
    __syncthreads();
    if (threadIdx.x == 0) {
        unsigned old = g_gen;
        __threadfence();
        if (atomicAdd(&g_cnt, 1u) == NB - 1) {
            g_cnt = 0;
            __threadfence();
            g_gen = old + 1;
        } else {
            while (g_gen == old) { }
        }
        __threadfence();
    }
    __syncthreads();
}

// =====================================================================
// xp0 (unchanged, known-good): emb[texts] @ Wih0^T + bih0
// =====================================================================
__global__ __launch_bounds__(256) void xp0_kernel(const int* __restrict__ texts,
                                                  const float* __restrict__ emb,
                                                  const float* __restrict__ Wih0,
                                                  const float* __restrict__ bih0) {
    __shared__ __align__(16) float sA [20 * 68];
    __shared__ __align__(16) float sW2[20 * 132];

    const int n0 = blockIdx.x * 64;
    const int m0 = blockIdx.y * 64;
    const int tid = threadIdx.x;
    const int mp = tid & 15;
    const int np = tid >> 4;

    unsigned long long acc[2][4];
#pragma unroll
    for (int a = 0; a < 2; a++)
#pragma unroll
        for (int j = 0; j < 4; j++) acc[a][j] = 0ull;

    for (int c = 0; c < 15; ++c) {
        const int kb = c * 20;
        __syncthreads();
        for (int idx = tid; idx < 320; idx += 256) {
            const int row = idx & 63;
            const int q   = idx >> 6;
            const int tok = texts[m0 + row];
            float4 v = *reinterpret_cast<const float4*>(emb + tok * EDIM + kb + 4 * q);
            sA[(4 * q + 0) * 68 + row] = v.x;
            sA[(4 * q + 1) * 68 + row] = v.y;
            sA[(4 * q + 2) * 68 + row] = v.z;
            sA[(4 * q + 3) * 68 + row] = v.w;
            float4 w = *reinterpret_cast<const float4*>(Wih0 + (n0 + row) * EDIM + kb + 4 * q);
            *reinterpret_cast<float2*>(&sW2[(4 * q + 0) * 132 + 2 * row]) = make_float2(w.x, w.x);
            *reinterpret_cast<float2*>(&sW2[(4 * q + 1) * 132 + 2 * row]) = make_float2(w.y, w.y);
            *reinterpret_cast<float2*>(&sW2[(4 * q + 2) * 132 + 2 * row]) = make_float2(w.z, w.z);
            *reinterpret_cast<float2*>(&sW2[(4 * q + 3) * 132 + 2 * row]) = make_float2(w.w, w.w);
        }
        __syncthreads();
#pragma unroll 5
        for (int kk = 0; kk < 20; ++kk) {
            ulonglong2 A  = *reinterpret_cast<const ulonglong2*>(&sA [kk * 68  + 4 * mp]);
            ulonglong2 Wa = *reinterpret_cast<const ulonglong2*>(&sW2[kk * 132 + 8 * np]);
            ulonglong2 Wb = *reinterpret_cast<const ulonglong2*>(&sW2[kk * 132 + 8 * np + 4]);
            acc[0][0] = fma2_(A.x, Wa.x, acc[0][0]);
            acc[0][1] = fma2_(A.x, Wa.y, acc[0][1]);
            acc[0][2] = fma2_(A.x, Wb.x, acc[0][2]);
            acc[0][3] = fma2_(A.x, Wb.y, acc[0][3]);
            acc[1][0] = fma2_(A.y, Wa.x, acc[1][0]);
            acc[1][1] = fma2_(A.y, Wa.y, acc[1][1]);
            acc[1][2] = fma2_(A.y, Wb.x, acc[1][2]);
            acc[1][3] = fma2_(A.y, Wb.y, acc[1][3]);
        }
    }

    float bi[4];
#pragma unroll
    for (int j = 0; j < 4; j++) bi[j] = bih0[n0 + 4 * np + j];
#pragma unroll
    for (int bp = 0; bp < 2; ++bp) {
        float2 u0 = unpack2_(acc[bp][0]);
        float2 u1 = unpack2_(acc[bp][1]);
        float2 u2 = unpack2_(acc[bp][2]);
        float2 u3 = unpack2_(acc[bp][3]);
        const int m = m0 + 4 * mp + 2 * bp;
        *reinterpret_cast<float4*>(&g_xp0[m * G3 + n0 + 4 * np]) =
            make_float4(u0.x + bi[0], u1.x + bi[1], u2.x + bi[2], u3.x + bi[3]);
        *reinterpret_cast<float4*>(&g_xp0[(m + 1) * G3 + n0 + 4 * np]) =
            make_float4(u0.y + bi[0], u1.y + bi[1], u2.y + bi[2], u3.y + bi[3]);
    }
}

// =====================================================================
// Gate nonlinearity (float4-vectorized), distributed across the grid.
// =====================================================================
#define LD4_(d, p)  { float4 _t = *reinterpret_cast<const float4*>(p); d[0]=_t.x; d[1]=_t.y; d[2]=_t.z; d[3]=_t.w; }
#define ADD4_(d, p) { float4 _t = *reinterpret_cast<const float4*>(p); d[0]+=_t.x; d[1]+=_t.y; d[2]+=_t.z; d[3]+=_t.w; }
#define ST4_(p, s)  { *reinterpret_cast<float4*>(p) = make_float4(s[0], s[1], s[2], s[3]); }

__device__ __forceinline__ void gate_phase(int iter, const float* bhh0,
                                           const float* bih1, const float* bhh1) {
    const int stride = NB * 256;
    for (int id = blockIdx.x * 256 + threadIdx.x; id < 2 * BATCH * HDIM / 4; id += stride) {
        const int layer = id >> 13;
        const int b = (id >> 7) & 63;
        const int h = (id & 127) * 4;
        const float* gha = g_gh + b * NCOLS;
        const float* ghb = g_gh + BATCH * NCOLS + b * NCOLS;

        if (layer == 0) {
            if (iter >= T_SEQ) continue;
            const float* xp = &g_xp0[(iter * BATCH + b) * G3];
            float xr[4], xz[4], xn[4], hr[4], hz[4], hn[4], hp[4], ho[4];
            LD4_(xr, xp + h); LD4_(xz, xp + HDIM + h); LD4_(xn, xp + 2 * HDIM + h);
            LD4_(hr, bhh0 + h); LD4_(hz, bhh0 + HDIM + h); LD4_(hn, bhh0 + 2 * HDIM + h);
            hp[0] = hp[1] = hp[2] = hp[3] = 0.0f;
            if (iter > 0) {
                ADD4_(hr, gha + h);            ADD4_(hr, ghb + h);
                ADD4_(hz, gha + HDIM + h);     ADD4_(hz, ghb + HDIM + h);
                ADD4_(hn, gha + 2 * HDIM + h); ADD4_(hn, ghb + 2 * HDIM + h);
                LD4_(hp, &g_h1h[((iter - 1) * BATCH + b) * HDIM + h]);
            }
#pragma unroll
            for (int j = 0; j < 4; j++) {
                float r = sigmoidf_(xr[j] + hr[j]);
                float z = sigmoidf_(xz[j] + hz[j]);
                float n = tanhf(xn[j] + r * hn[j]);
                ho[j] = (1.0f - z) * n + z * hp[j];
            }
            ST4_(&g_h1h[(iter * BATCH + b) * HDIM + h], ho);
        } else {
            if (iter < 1) continue;
            const int t = iter - 1;
            float xr[4], xz[4], xn[4], hr[4], hz[4], hn[4], hp[4], ho[4];
            LD4_(xr, bih1 + h); LD4_(xz, bih1 + HDIM + h); LD4_(xn, bih1 + 2 * HDIM + h);
            ADD4_(xr, gha + G3 + h);            ADD4_(xr, ghb + G3 + h);
            ADD4_(xz, gha + G3 + HDIM + h);     ADD4_(xz, ghb + G3 + HDIM + h);
            ADD4_(xn, gha + G3 + 2 * HDIM + h); ADD4_(xn, ghb + G3 + 2 * HDIM + h);
            LD4_(hr, bhh1 + h); LD4_(hz, bhh1 + HDIM + h); LD4_(hn, bhh1 + 2 * HDIM + h);
            hp[0] = hp[1] = hp[2] = hp[3] = 0.0f;
            if (t > 0) {
                ADD4_(hr, gha + 2 * G3 + h);            ADD4_(hr, ghb + 2 * G3 + h);
                ADD4_(hz, gha + 2 * G3 + HDIM + h);     ADD4_(hz, ghb + 2 * G3 + HDIM + h);
                ADD4_(hn, gha + 2 * G3 + 2 * HDIM + h); ADD4_(hn, ghb + 2 * G3 + 2 * HDIM + h);
                LD4_(hp, &g_h2h[((t - 1) * BATCH + b) * HDIM + h]);
            }
#pragma unroll
            for (int j = 0; j < 4; j++) {
                float r = sigmoidf_(xr[j] + hr[j]);
                float z = sigmoidf_(xz[j] + hz[j]);
                float n = tanhf(xn[j] + r * hn[j]);
                ho[j] = (1.0f - z) * n + z * hp[j];
            }
            ST4_(&g_h2h[(t * BATCH + b) * HDIM + h], ho);
        }
    }
}

// =====================================================================
// Persistent warp-MMA recurrence. 144 CTAs = 72 n-tiles(64) x 2 K-halves(256).
// bf16 hi/lo split: D = Ah*Bh + Al*Bh + Ah*Bl, fp32 accumulate in registers.
// SMEM (bytes): Ah [64][264] | Al | Bh [64n][264] | Bl  (stride 528B, LDSM conflict-free)
// =====================================================================
#define ASTRIDE 528                 // bytes per row (264 bf16)
#define SM_AH   0
#define SM_AL   (64 * ASTRIDE)      // 33792
#define SM_BH   (2 * 64 * ASTRIDE)  // 67584
#define SM_BL   (3 * 64 * ASTRIDE)  // 101376
#define SMEM_REC (4 * 64 * ASTRIDE) // 135168 -> 1 CTA/SM

__global__ __launch_bounds__(256) void recurrence_kernel(const float* __restrict__ Whh0,
                                                         const float* __restrict__ Wih1,
                                                         const float* __restrict__ Whh1,
                                                         const float* bhh0,
                                                         const float* bih1,
                                                         const float* bhh1) {
    extern __shared__ char sm[];
    const uint32_t sb = smem_u32_(sm);
    const int tid = threadIdx.x;
    const int wid = tid >> 5;
    const int lane = tid & 31;
    const int cta = blockIdx.x;
    const int nt0 = cta % 72;
    const int kt  = cta / 72;
    const int n0  = nt0 * 64;
    const int k0  = kt * 256;

    const float* W;
    int wr0, cls;
    if (n0 < G3)          { W = Whh0; wr0 = n0;          cls = 0; }
    else if (n0 < 2 * G3) { W = Wih1; wr0 = n0 - G3;     cls = 1; }
    else                  { W = Whh1; wr0 = n0 - 2 * G3; cls = 2; }

    // ---- prologue: weight tile (64 n-rows x 256 k) -> bf16 hi/lo in SMEM ----
    for (int idx = tid; idx < 4096; idx += 256) {
        const int row = idx >> 6;        // n within tile
        const int q   = idx & 63;        // k/4
        float4 v = *reinterpret_cast<const float4*>(W + (wr0 + row) * HDIM + k0 + 4 * q);
        uint2 hi, lo;
        split_hl_(v, hi, lo);
        *reinterpret_cast<uint2*>(sm + SM_BH + row * ASTRIDE + 8 * q) = hi;
        *reinterpret_cast<uint2*>(sm + SM_BL + row * ASTRIDE + 8 * q) = lo;
    }
    __syncthreads();

    // per-warp MMA geometry: 16 m-rows x 32 n-cols
    const int mrow = (wid & 3) * 16;
    const int nco  = (wid >> 2) * 32;
    const uint32_t aoff = sb + (uint32_t)((mrow + (lane & 15)) * ASTRIDE + (lane >> 4) * 16);
    const uint32_t boff = sb + (uint32_t)((nco + (lane & 7)) * ASTRIDE + ((lane >> 3) & 1) * 16);

    for (int iter = 0; iter <= T_SEQ; ++iter) {
        const bool active = (iter > 0) && !(cls == 0 && iter > 511) && !(cls == 2 && iter < 2);
        if (active) {
            const float* hsrc = (cls == 2) ? g_h2h + (iter - 2) * BATCH * HDIM
                                           : g_h1h + (iter - 1) * BATCH * HDIM;
            // fill A (64 batch rows x 256 k) as bf16 hi/lo
            for (int idx = tid; idx < 4096; idx += 256) {
                const int row = idx >> 6;
                const int q   = idx & 63;
                float4 v = *reinterpret_cast<const float4*>(hsrc + row * HDIM + k0 + 4 * q);
                uint2 hi, lo;
                split_hl_(v, hi, lo);
                *reinterpret_cast<uint2*>(sm + SM_AH + row * ASTRIDE + 8 * q) = hi;
                *reinterpret_cast<uint2*>(sm + SM_AL + row * ASTRIDE + 8 * q) = lo;
            }
            __syncthreads();

            float acc[4][4];
#pragma unroll
            for (int t = 0; t < 4; t++)
#pragma unroll
                for (int j = 0; j < 4; j++) acc[t][j] = 0.0f;

            const uint32_t aBase[3] = { aoff + SM_AH, aoff + SM_AL, aoff + SM_AH };
            const uint32_t bBase[3] = { boff + SM_BH, boff + SM_BH, boff + SM_BL };
#pragma unroll
            for (int term = 0; term < 3; ++term) {
                const uint32_t ab = aBase[term];
                const uint32_t bb = bBase[term];
#pragma unroll
                for (int ks = 0; ks < 16; ++ks) {
                    uint32_t a0, a1, a2, a3;
                    ldsm4_(a0, a1, a2, a3, ab + ks * 32);
#pragma unroll
                    for (int nt = 0; nt < 4; ++nt) {
                        uint32_t b0, b1;
                        ldsm2_(b0, b1, bb + nt * 8 * ASTRIDE + ks * 32);
                        mma16816_(acc[nt], a0, a1, a2, a3, b0, b1);
                    }
                }
            }

            // epilogue: write partials to g_gh
            const int crow = lane >> 2;
            const int ccol = (lane & 3) * 2;
            float* outp = g_gh + kt * BATCH * NCOLS;
#pragma unroll
            for (int nt = 0; nt < 4; ++nt) {
                const int n = n0 + nco + nt * 8 + ccol;
                const int b = mrow + crow;
                *reinterpret_cast<float2*>(outp + b * NCOLS + n) =
                    make_float2(acc[nt][0], acc[nt][1]);
                *reinterpret_cast<float2*>(outp + (b + 8) * NCOLS + n) =
                    make_float2(acc[nt][2], acc[nt][3]);
            }
        }
        grid_sync();                         // partials visible
        gate_phase(iter, bhh0, bih1, bhh1);
        grid_sync();                         // h1/h2 visible
    }
}

// =====================================================================
// pooled[t][h] = mean_b h2[t][b][h];  out[t][l] = pooled . fc_W[l] + fc_b[l]
// =====================================================================
__global__ __launch_bounds__(512) void final_kernel(const float* __restrict__ fc_W,
                                                    const float* __restrict__ fc_b,
                                                    float* __restrict__ out) {
    __shared__ float pooled[HDIM];
    const int t = blockIdx.x;
    const int h = threadIdx.x;

    float s = 0.0f;
    const float* base = &g_h2h[t * BATCH * HDIM + h];
#pragma unroll 8
    for (int b = 0; b < BATCH; ++b) s += base[b * HDIM];
    pooled[h] = s * (1.0f / (float)BATCH);
    __syncthreads();

    const int w = h >> 5, lane = h & 31;
    if (w < 5) {
        float acc = 0.0f;
        for (int k = lane; k < HDIM; k += 32) acc += pooled[k] * fc_W[w * HDIM + k];
#pragma unroll
        for (int o = 16; o > 0; o >>= 1) acc += __shfl_xor_sync(0xFFFFFFFFu, acc, o);
        if (lane == 0) out[t * 5 + w] = acc + fc_b[w];
    }
}

// =====================================================================
extern "C" void kernel_launch(void* const* d_in, const int* in_sizes, int n_in,
                              void* d_out, int out_size) {
    const int*   texts = (const int*)  d_in[0];
    const float* emb   = (const float*)d_in[1];
    const float* Wih0  = (const float*)d_in[2];
    const float* Whh0  = (const float*)d_in[3];
    const float* bih0  = (const float*)d_in[4];
    const float* bhh0  = (const float*)d_in[5];
    const float* Wih1  = (const float*)d_in[6];
    const float* Whh1  = (const float*)d_in[7];
    const float* bih1  = (const float*)d_in[8];
    const float* bhh1  = (const float*)d_in[9];
    const float* fc_W  = (const float*)d_in[10];
    const float* fc_b  = (const float*)d_in[11];
    float* out = (float*)d_out;

    cudaFuncSetAttribute(recurrence_kernel,
                         cudaFuncAttributeMaxDynamicSharedMemorySize, SMEM_REC);

    xp0_kernel<<<dim3(24, 512), 256>>>(texts, emb, Wih0, bih0);
    recurrence_kernel<<<NB, 256, SMEM_REC>>>(Whh0, Wih1, Whh1, bhh0, bih1, bhh1);
    final_kernel<<<T_SEQ, 512>>>(fc_W, fc_b, out);
}